// round 13
// baseline (speedup 1.0000x reference)
#include <cuda_runtime.h>
#include <math.h>

#define FDIM 128
#define GMAX 50000
#define SEGB 32          // segments per MLP block
#define PAD  36          // spT row stride (floats): 16B-aligned, conflict-free

// ---------------- device scratch (zero-initialized .bss; self-restoring) ----------------
// g_pool starts zero (.bss); the MLP kernel re-zeroes it after consuming it,
// so every graph replay sees zeros again. L2-resident (25.6 MB << 126 MB L2).
__device__ float g_pool[(size_t)GMAX * FDIM];

__device__ __forceinline__ float tanh_fast(float x) {
    float r;
    asm("tanh.approx.f32 %0, %1;" : "=f"(r) : "f"(x));
    return r;
}

typedef unsigned long long ull;

__device__ __forceinline__ ull dup2(float x) {           // {x, x} as f32x2
    ull r;
    asm("mov.b64 %0, {%1, %1};" : "=l"(r) : "f"(x));
    return r;
}
__device__ __forceinline__ void fma2(ull& d, ull a, ull b) {  // d = a*b + d (lanewise f32)
    asm("fma.rn.f32x2 %0, %1, %2, %3;" : "=l"(d) : "l"(a), "l"(b), "l"(d));
}
__device__ __forceinline__ void unpack2(float& lo, float& hi, ull v) {
    asm("mov.b64 {%0, %1}, %2;" : "=f"(lo), "=f"(hi) : "l"(v));
}

// ---------------- kernel 1: stream h in node order, scatter-add into L2 pool ----------------
__global__ void __launch_bounds__(256) stream_pool_kernel(
    const float* __restrict__ h,
    const void*  __restrict__ seg,
    int N)
{
    __shared__ int s_is64;
    if (threadIdx.x == 0) {
        // int64 ids < 2^32 have zero high words; 64 random int32 ids all-zero: p ~ 0
        const unsigned int* w = (const unsigned int*)seg;
        unsigned int acc = 0;
        #pragma unroll
        for (int k = 0; k < 64; k++) acc |= w[2 * k + 1];
        s_is64 = (acc == 0u) ? 1 : 0;
    }
    __syncthreads();
    const int is64 = s_is64;

    const int warp = threadIdx.x >> 5;
    const int lane = threadIdx.x & 31;
    const int base = (blockIdx.x * 8 + warp) * 32;   // 32 consecutive nodes per warp
    if (base >= N) return;                           // uniform per warp
    const int cnt = min(32, N - base);

    int sid = 0;
    if (lane < cnt) {
        sid = is64 ? (int)((const long long*)seg)[base + lane]
                   : ((const int*)seg)[base + lane];
    }

    #pragma unroll 4
    for (int j = 0; j < 32; j++) {
        if (j >= cnt) break;
        const int s = __shfl_sync(0xffffffffu, sid, j);
        float4 v = __ldcs((const float4*)(h + (size_t)(base + j) * FDIM) + lane);
        float* dst = g_pool + (size_t)s * FDIM + lane * 4;
        asm volatile("red.global.add.v4.f32 [%0], {%1, %2, %3, %4};"
                     :: "l"(dst), "f"(v.x), "f"(v.y), "f"(v.z), "f"(v.w)
                     : "memory");
    }
}

// ---------------- kernel 2: MLP head, 32 segments/block, f32x2 FMA ----------------
// Warp w owns segs s0..s0+3 (s0 = 4w) and, per lane, cols 4l..4l+3.
// Per k: 1 coalesced LDG.128 (W1 row) + 4 dup + 1 broadcast LDS.128 (4 seg
// values = 2 f32x2 pairs, used in place) + 8 fma.rn.f32x2 = 14 instr / 16 FMA.
__global__ void __launch_bounds__(256, 5) mlp_kernel(
    const float* __restrict__ W1,   // [128,128] row-major: W1[k][c]
    const float* __restrict__ b1,   // [128]
    const float* __restrict__ W2,   // [128]
    const float* __restrict__ b2,   // [1]
    float* __restrict__ y, int G)
{
    __shared__ float spT[FDIM][PAD];    // transposed pooled tile (18.4 KB)
    __shared__ float sy[SEGB];

    const int tid  = threadIdx.x;
    const int warp = tid >> 5;
    const int lane = tid & 31;
    const int gbase = blockIdx.x * SEGB;

    // ---- transpose-load pooled tile; zero g_pool behind us ----
    const float4 z4 = make_float4(0.f, 0.f, 0.f, 0.f);
    #pragma unroll
    for (int it = 0; it < 4; it++) {
        int idx = it * 256 + tid;       // 0..1023
        int k4  = idx >> 5;             // float4 chunk 0..31
        int s   = idx & 31;
        int g   = gbase + s;
        float4 v = z4;
        if (g < G) {
            float4* p = (float4*)(g_pool + (size_t)g * FDIM) + k4;
            v = *p;
            *p = z4;                    // self-restore for the next replay
        }
        spT[4 * k4 + 0][s] = v.x;       // bank = (36*(4k4+j) + s) & 31, s consecutive -> conflict-free
        spT[4 * k4 + 1][s] = v.y;
        spT[4 * k4 + 2][s] = v.z;
        spT[4 * k4 + 3][s] = v.w;
    }
    __syncthreads();

    // ---- register-tiled GEMM: 4 segs (2 f32x2 pairs) x 4 cols per thread ----
    const int s0 = warp * 4;
    float4 bb = __ldg((const float4*)b1 + lane);    // b1[4l..4l+3]
    ull acc[2][4];                                  // [segpair][col]
    {
        ull i0 = dup2(bb.x), i1 = dup2(bb.y), i2 = dup2(bb.z), i3 = dup2(bb.w);
        acc[0][0] = i0; acc[0][1] = i1; acc[0][2] = i2; acc[0][3] = i3;
        acc[1][0] = i0; acc[1][1] = i1; acc[1][2] = i2; acc[1][3] = i3;
    }

    #pragma unroll 4
    for (int k = 0; k < FDIM; k++) {
        float4 wv = __ldg((const float4*)(W1 + k * FDIM) + lane);   // W1[k][4l..4l+3]
        ull w0 = dup2(wv.x), w1 = dup2(wv.y), w2d = dup2(wv.z), w3 = dup2(wv.w);
        ulonglong2 q = *(const ulonglong2*)&spT[k][s0];     // {s0,s1},{s2,s3} broadcast
        fma2(acc[0][0], q.x, w0); fma2(acc[0][1], q.x, w1);
        fma2(acc[0][2], q.x, w2d); fma2(acc[0][3], q.x, w3);
        fma2(acc[1][0], q.y, w0); fma2(acc[1][1], q.y, w1);
        fma2(acc[1][2], q.y, w2d); fma2(acc[1][3], q.y, w3);
    }

    // ---- epilogue: tanh, dot with W2 over this thread's 4 cols, warp-reduce ----
    float4 w2 = __ldg((const float4*)W2 + lane);
    const float w2a[4] = {w2.x, w2.y, w2.z, w2.w};
    float psum[4];
    #pragma unroll
    for (int qp = 0; qp < 2; qp++) {
        float pe = 0.f, po = 0.f;
        #pragma unroll
        for (int c = 0; c < 4; c++) {
            float lo, hi;
            unpack2(lo, hi, acc[qp][c]);
            pe = fmaf(tanh_fast(lo), w2a[c], pe);
            po = fmaf(tanh_fast(hi), w2a[c], po);
        }
        psum[2 * qp]     = pe;
        psum[2 * qp + 1] = po;
    }
    #pragma unroll
    for (int off = 16; off; off >>= 1) {
        #pragma unroll
        for (int s = 0; s < 4; s++)
            psum[s] += __shfl_down_sync(0xffffffffu, psum[s], off);
    }
    if (lane == 0) {
        #pragma unroll
        for (int s = 0; s < 4; s++) sy[s0 + s] = psum[s];
    }
    __syncthreads();

    if (tid < SEGB) {
        int g = gbase + tid;
        if (g < G) y[g] = sy[tid] + __ldg(b2);
    }
}

// ---------------- launch ----------------
extern "C" void kernel_launch(void* const* d_in, const int* in_sizes, int n_in,
                              void* d_out, int out_size) {
    const float* h   = (const float*)d_in[0];
    const void*  seg = d_in[1];
    const int N = in_sizes[0] / FDIM;
    const int G = out_size;          // OUT = 1

    int iw = -1;
    for (int i = 2; i < n_in; i++) {
        if (in_sizes[i] == FDIM * FDIM) { iw = i; break; }
    }
    const float* W1 = (const float*)d_in[iw];
    const float* b1 = (const float*)d_in[iw + 1];
    const float* W2 = (const float*)d_in[iw + 2];
    const float* b2 = (const float*)d_in[iw + 3];
    float* y = (float*)d_out;

    const int nodes_per_blk = 8 * 32;    // 8 warps x 32 nodes
    stream_pool_kernel<<<(N + nodes_per_blk - 1) / nodes_per_blk, 256>>>(h, seg, N);
    mlp_kernel<<<(G + SEGB - 1) / SEGB, 256>>>(W1, b1, W2, b2, y, G);
}

// round 14
// speedup vs baseline: 1.2837x; 1.2837x over previous
#include <cuda_runtime.h>
#include <math.h>

#define FDIM 128
#define GMAX 50000
#define SEGB 64          // segments per MLP block
#define PAD  132         // sA row stride (floats): frag reads conflict-free

// ---------------- device scratch (zero-initialized .bss; self-restoring) ----------------
__device__ float g_pool[(size_t)GMAX * FDIM];

__device__ __forceinline__ float tanh_fast(float x) {
    float r;
    asm("tanh.approx.f32 %0, %1;" : "=f"(r) : "f"(x));
    return r;
}

// tf32 split: hi = truncate-to-tf32(x) (exact), lo = x - hi (exact), then truncate lo.
__device__ __forceinline__ void tf32_split(float x, unsigned& hi, unsigned& lo) {
    unsigned bx = __float_as_uint(x);
    hi = bx & 0xFFFFE000u;
    float lof = x - __uint_as_float(hi);
    lo = __float_as_uint(lof) & 0xFFFFE000u;
}

__device__ __forceinline__ void mma_tf32(
    float& d0, float& d1, float& d2, float& d3,
    unsigned a0, unsigned a1, unsigned a2, unsigned a3,
    unsigned b0, unsigned b1)
{
    asm volatile(
        "mma.sync.aligned.m16n8k8.row.col.f32.tf32.tf32.f32 "
        "{%0,%1,%2,%3}, {%4,%5,%6,%7}, {%8,%9}, {%0,%1,%2,%3};"
        : "+f"(d0), "+f"(d1), "+f"(d2), "+f"(d3)
        : "r"(a0), "r"(a1), "r"(a2), "r"(a3), "r"(b0), "r"(b1));
}

// ---------------- kernel 1: stream h in node order, scatter-add into L2 pool ----------------
__global__ void __launch_bounds__(256) stream_pool_kernel(
    const float* __restrict__ h,
    const void*  __restrict__ seg,
    int N)
{
    __shared__ int s_is64;
    if (threadIdx.x == 0) {
        const unsigned int* w = (const unsigned int*)seg;
        unsigned int acc = 0;
        #pragma unroll
        for (int k = 0; k < 64; k++) acc |= w[2 * k + 1];
        s_is64 = (acc == 0u) ? 1 : 0;
    }
    __syncthreads();
    const int is64 = s_is64;

    const int warp = threadIdx.x >> 5;
    const int lane = threadIdx.x & 31;
    const int base = (blockIdx.x * 8 + warp) * 32;   // 32 consecutive nodes per warp
    if (base >= N) return;                           // uniform per warp
    const int cnt = min(32, N - base);

    int sid = 0;
    if (lane < cnt) {
        sid = is64 ? (int)((const long long*)seg)[base + lane]
                   : ((const int*)seg)[base + lane];
    }

    #pragma unroll 4
    for (int j = 0; j < 32; j++) {
        if (j >= cnt) break;
        const int s = __shfl_sync(0xffffffffu, sid, j);
        float4 v = __ldcs((const float4*)(h + (size_t)(base + j) * FDIM) + lane);
        float* dst = g_pool + (size_t)s * FDIM + lane * 4;
        asm volatile("red.global.add.v4.f32 [%0], {%1, %2, %3, %4};"
                     :: "l"(dst), "f"(v.x), "f"(v.y), "f"(v.z), "f"(v.w)
                     : "memory");
    }
}

// ---------------- kernel 2: tensor-core MLP head ----------------
// Block: 64 segments x 128 cols. Warp w: seg stripe mrow=w&3 (16 segs), col half
// nhalf=w>>2 (64 cols = 8 n-tiles). tf32 mma with 3-term compensation (fp32-grade).
__global__ void __launch_bounds__(256) mlp_kernel(
    const float* __restrict__ W1,   // [128,128] row-major: W1[k][c]
    const float* __restrict__ b1,   // [128]
    const float* __restrict__ W2,   // [128]
    const float* __restrict__ b2,   // [1]
    float* __restrict__ y, int G)
{
    __shared__ float sA[SEGB][PAD];     // pooled tile (33.8 KB)
    __shared__ float sy[SEGB][2];

    const int tid  = threadIdx.x;
    const int warp = tid >> 5;
    const int lane = tid & 31;
    const int gid  = lane >> 2;         // group id 0..7
    const int tig  = lane & 3;          // thread in group 0..3
    const int mrow  = warp & 3;         // seg stripe (16 segs)
    const int nhalf = warp >> 2;        // column half (64 cols)
    const int gbase = blockIdx.x * SEGB;

    // ---- load pooled tile into smem; zero g_pool behind us ----
    const float4 z4 = make_float4(0.f, 0.f, 0.f, 0.f);
    #pragma unroll
    for (int it = 0; it < 8; it++) {
        int idx = it * 256 + tid;       // 0..2047 = 64 segs x 32 float4
        int s = idx >> 5;
        int c = idx & 31;
        int g = gbase + s;
        float4 v = z4;
        if (g < G) {
            float4* p = (float4*)(g_pool + (size_t)g * FDIM) + c;
            v = *p;
            *p = z4;                    // self-restore for the next replay
        }
        sA[s][4 * c + 0] = v.x;
        sA[s][4 * c + 1] = v.y;
        sA[s][4 * c + 2] = v.z;
        sA[s][4 * c + 3] = v.w;
    }
    __syncthreads();

    // ---- mma mainloop: 16 k-steps x 8 n-tiles, 3-term tf32 compensation ----
    float d[8][4];
    #pragma unroll
    for (int nt = 0; nt < 8; nt++)
        d[nt][0] = d[nt][1] = d[nt][2] = d[nt][3] = 0.f;

    const int sbase = mrow * 16;
    #pragma unroll 2
    for (int k0 = 0; k0 < FDIM; k0 += 8) {
        // A fragments (m16n8k8 row-major): a0:(gid,tig) a1:(gid+8,tig) a2:(gid,tig+4) a3:(gid+8,tig+4)
        float fa0 = sA[sbase + gid][k0 + tig];
        float fa1 = sA[sbase + gid + 8][k0 + tig];
        float fa2 = sA[sbase + gid][k0 + tig + 4];
        float fa3 = sA[sbase + gid + 8][k0 + tig + 4];
        unsigned a0h, a0l, a1h, a1l, a2h, a2l, a3h, a3l;
        tf32_split(fa0, a0h, a0l);
        tf32_split(fa1, a1h, a1l);
        tf32_split(fa2, a2h, a2l);
        tf32_split(fa3, a3h, a3l);

        #pragma unroll
        for (int nt = 0; nt < 8; nt++) {
            const int n0 = nhalf * 64 + nt * 8;
            // B fragments (col-major 8x8): b0:(k=tig, n=gid) b1:(k=tig+4, n=gid)
            float fb0 = __ldg(W1 + (k0 + tig) * FDIM + n0 + gid);
            float fb1 = __ldg(W1 + (k0 + tig + 4) * FDIM + n0 + gid);
            unsigned b0h, b0l, b1h, b1l;
            tf32_split(fb0, b0h, b0l);
            tf32_split(fb1, b1h, b1l);

            mma_tf32(d[nt][0], d[nt][1], d[nt][2], d[nt][3],
                     a0h, a1h, a2h, a3h, b0h, b1h);
            mma_tf32(d[nt][0], d[nt][1], d[nt][2], d[nt][3],
                     a0l, a1l, a2l, a3l, b0h, b1h);
            mma_tf32(d[nt][0], d[nt][1], d[nt][2], d[nt][3],
                     a0h, a1h, a2h, a3h, b0l, b1l);
        }
    }

    // ---- epilogue: bias, tanh, W2 dot, reduce over tig group (width 4) ----
    float p0 = 0.f, p1 = 0.f;          // rows gid, gid+8 of this stripe
    #pragma unroll
    for (int nt = 0; nt < 8; nt++) {
        const int c0 = nhalf * 64 + nt * 8 + 2 * tig;
        float bb0 = __ldg(b1 + c0),     bb1 = __ldg(b1 + c0 + 1);
        float w20 = __ldg(W2 + c0),     w21 = __ldg(W2 + c0 + 1);
        p0 = fmaf(tanh_fast(d[nt][0] + bb0), w20, p0);
        p0 = fmaf(tanh_fast(d[nt][1] + bb1), w21, p0);
        p1 = fmaf(tanh_fast(d[nt][2] + bb0), w20, p1);
        p1 = fmaf(tanh_fast(d[nt][3] + bb1), w21, p1);
    }
    p0 += __shfl_down_sync(0xffffffffu, p0, 2, 4);
    p0 += __shfl_down_sync(0xffffffffu, p0, 1, 4);
    p1 += __shfl_down_sync(0xffffffffu, p1, 2, 4);
    p1 += __shfl_down_sync(0xffffffffu, p1, 1, 4);
    if (tig == 0) {
        sy[sbase + gid][nhalf]     = p0;
        sy[sbase + gid + 8][nhalf] = p1;
    }
    __syncthreads();

    if (tid < SEGB) {
        int g = gbase + tid;
        if (g < G) y[g] = sy[tid][0] + sy[tid][1] + __ldg(b2);
    }
}

// ---------------- launch ----------------
extern "C" void kernel_launch(void* const* d_in, const int* in_sizes, int n_in,
                              void* d_out, int out_size) {
    const float* h   = (const float*)d_in[0];
    const void*  seg = d_in[1];
    const int N = in_sizes[0] / FDIM;
    const int G = out_size;          // OUT = 1

    int iw = -1;
    for (int i = 2; i < n_in; i++) {
        if (in_sizes[i] == FDIM * FDIM) { iw = i; break; }
    }
    const float* W1 = (const float*)d_in[iw];
    const float* b1 = (const float*)d_in[iw + 1];
    const float* W2 = (const float*)d_in[iw + 2];
    const float* b2 = (const float*)d_in[iw + 3];
    float* y = (float*)d_out;

    const int nodes_per_blk = 8 * 32;    // 8 warps x 32 nodes
    stream_pool_kernel<<<(N + nodes_per_blk - 1) / nodes_per_blk, 256>>>(h, seg, N);
    mlp_kernel<<<(G + SEGB - 1) / SEGB, 256>>>(W1, b1, W2, b2, y, G);
}